// round 15
// baseline (speedup 1.0000x reference)
#include <cuda_runtime.h>

#define K          84
#define CHUNKS     21
#define NPROTO     10
#define THREADS    128           // 4 warps per CTA
#define NWARPS     4
#define SLOT_ROWS  32
#define SLOT_FLOATS (SLOT_ROWS * K)          // 2688
#define SLOT_BYTES  (SLOT_FLOATS * 4)        // 10752
#define NSLOTS     8                          // 4 warps x 2 bufs
#define KSTEPS     11                         // ceil(84/8)

// smem per CTA: slots[8][SLOT_FLOATS] + w2[16] + mbar[8] -> ~86.2 KB, 2 CTAs/SM
#define SMEM_BYTES (NSLOTS * SLOT_BYTES + 64 + 64)

__device__ __forceinline__ void ffma2(unsigned long long &d,
                                      unsigned long long a,
                                      unsigned long long b) {
    asm("fma.rn.f32x2 %0, %1, %2, %0;" : "+l"(d) : "l"(a), "l"(b));
}
__device__ __forceinline__ float f2lo(unsigned long long v) {
    return __int_as_float((unsigned)(v & 0xffffffffULL));
}
__device__ __forceinline__ float f2hi(unsigned long long v) {
    return __int_as_float((unsigned)(v >> 32));
}

__device__ __forceinline__ void mma_tf32(float &d0, float &d1, float &d2, float &d3,
                                         unsigned a0, unsigned a1, unsigned a2, unsigned a3,
                                         unsigned b0, unsigned b1) {
    asm("mma.sync.aligned.m16n8k8.row.col.f32.tf32.tf32.f32 "
        "{%0,%1,%2,%3},{%4,%5,%6,%7},{%8,%9},{%0,%1,%2,%3};"
        : "+f"(d0), "+f"(d1), "+f"(d2), "+f"(d3)
        : "r"(a0), "r"(a1), "r"(a2), "r"(a3), "r"(b0), "r"(b1));
}

__device__ __forceinline__ void mbar_init(unsigned mbar, unsigned count) {
    asm volatile("mbarrier.init.shared.b64 [%0], %1;" :: "r"(mbar), "r"(count) : "memory");
}
__device__ __forceinline__ void mbar_expect_tx(unsigned mbar, unsigned bytes) {
    asm volatile("mbarrier.arrive.expect_tx.shared.b64 _, [%0], %1;"
                 :: "r"(mbar), "r"(bytes) : "memory");
}
__device__ __forceinline__ void mbar_wait(unsigned mbar, unsigned parity) {
    unsigned done;
    asm volatile(
        "{\n\t"
        ".reg .pred p;\n\t"
        "mbarrier.try_wait.parity.acquire.cta.shared::cta.b64 p, [%1], %2;\n\t"
        "selp.b32 %0, 1, 0, p;\n\t"
        "}" : "=r"(done) : "r"(mbar), "r"(parity) : "memory");
    if (!done) {
        asm volatile(
            "{\n\t"
            ".reg .pred P1;\n\t"
            "WAIT_LOOP_%=:\n\t"
            "mbarrier.try_wait.parity.acquire.cta.shared::cta.b64 P1, [%0], %1, 0x989680;\n\t"
            "@P1 bra.uni WAIT_DONE_%=;\n\t"
            "bra.uni WAIT_LOOP_%=;\n\t"
            "WAIT_DONE_%=:\n\t"
            "}" :: "r"(mbar), "r"(parity) : "memory");
    }
}
__device__ __forceinline__ void bulk_g2s(unsigned dst_smem, const void* src,
                                         unsigned bytes, unsigned mbar) {
    asm volatile(
        "cp.async.bulk.shared::cta.global.mbarrier::complete_tx::bytes "
        "[%0], [%1], %2, [%3];"
        :: "r"(dst_smem), "l"(src), "r"(bytes), "r"(mbar) : "memory");
}

__global__ void __launch_bounds__(THREADS, 2)
rbf_kernel(const float* __restrict__ x,
           const float* __restrict__ weight,
           float* __restrict__ out,
           int nrows) {
    extern __shared__ __align__(16) float smem[];
    float* s_slots = smem;                                     // [8][SLOT_FLOATS]
    float* s_w2    = smem + NSLOTS * SLOT_FLOATS;              // [16]
    unsigned long long* s_mbar = (unsigned long long*)(s_w2 + 16); // [8]

    const int t    = threadIdx.x;
    const int lane = t & 31;
    const int warp = t >> 5;       // 0..3
    const int lg   = lane >> 2;    // 0..7
    const int lc   = lane & 3;     // 0..3

    // ---- B fragments in registers (row.col): proto = nt*8+lg, k = s*8+lc ----
    unsigned Bf[2][KSTEPS][2];
    #pragma unroll
    for (int nt = 0; nt < 2; nt++) {
        int proto = nt * 8 + lg;
        bool pv = proto < NPROTO;
        #pragma unroll
        for (int s = 0; s < KSTEPS; s++) {
            int k0 = s * 8 + lc;
            Bf[nt][s][0] = (pv && k0 < K)     ? __float_as_uint(weight[proto * K + k0])     : 0u;
            Bf[nt][s][1] = (pv && k0 + 4 < K) ? __float_as_uint(weight[proto * K + k0 + 4]) : 0u;
        }
    }

    if (t < NPROTO) {
        float s = 0.f;
        #pragma unroll
        for (int j = 0; j < K; j++) { float w = weight[t * K + j]; s += w * w; }
        s_w2[t] = s;
    }
    if (t >= NPROTO && t < 16) s_w2[t] = 0.f;

    const unsigned mb_base = (unsigned)__cvta_generic_to_shared(&s_mbar[0]);
    const unsigned sl_base = (unsigned)__cvta_generic_to_shared(s_slots);
    if (t < NSLOTS) mbar_init(mb_base + t * 8, 1);

    __syncthreads();   // w2 + mbarriers visible; last block sync

    const int   c0   = 2 * lc;
    const float w2a  = s_w2[c0];
    const float w2b  = s_w2[c0 + 1];
    const float w2p8 = s_w2[8];
    const float w2p9 = s_w2[9];

    const int nstages = (nrows + SLOT_ROWS - 1) / SLOT_ROWS;  // 16384
    const int step = gridDim.x;                               // 2*nsm
    int count = 0;
    for (long long s = blockIdx.x; s < nstages; s += step) count++;

    // warp-private: slot index = warp*2 + buf
    auto issue_stage = [&](int j, int buf) {
        if (lane == 0 && j < count) {
            int slot = warp * 2 + buf;
            long long stage = (long long)blockIdx.x + (long long)j * step;
            long long row0 = stage * SLOT_ROWS;
            long long rem_rows = (long long)nrows - row0;
            unsigned bytes = (rem_rows >= SLOT_ROWS)
                           ? SLOT_BYTES
                           : (unsigned)(rem_rows * K * 4);
            mbar_expect_tx(mb_base + slot * 8, bytes);
            bulk_g2s(sl_base + slot * SLOT_BYTES, x + row0 * K, bytes,
                     mb_base + slot * 8);
        }
    };

    // ---- prologue: each warp fills its two private slots ----
    issue_stage(warp,          0);
    issue_stage(warp + NWARPS, 1);

    int jj = warp;
    int buf = 0;
    int par0 = 0, par1 = 0;

    while (jj < count) {
        const int slot = warp * 2 + buf;
        const int par = buf ? par1 : par0;
        mbar_wait(mb_base + slot * 8, (unsigned)par);
        if (buf) par1 ^= 1; else par0 ^= 1;

        const long long stage = (long long)blockIdx.x + (long long)jj * step;
        const float* sx = s_slots + slot * SLOT_FLOATS;

        // ---- x2: one row per lane ----
        float x2r;
        {
            const ulonglong2* rp = (const ulonglong2*)(sx + lane * K);
            unsigned long long a0 = 0ULL, a1 = 0ULL;
            #pragma unroll
            for (int c = 0; c < CHUNKS; c++) {
                ulonglong2 v = rp[c];
                ffma2(a0, v.x, v.x);
                ffma2(a1, v.y, v.y);
            }
            x2r = (f2lo(a0) + f2hi(a0)) + (f2lo(a1) + f2hi(a1));
        }

        // ---- two 16-row MMA tiles (rows 0-15, 16-31 of slot) ----
        #pragma unroll
        for (int mt = 0; mt < 2; mt++) {
            const float* ap0 = sx + (mt * 16 + lg) * K + lc;
            const float* ap1 = ap0 + 8 * K;

            float dA0 = 0.f, dA1 = 0.f, dA2 = 0.f, dA3 = 0.f;
            float dB0 = 0.f, dB1 = 0.f, dB2 = 0.f, dB3 = 0.f;
            float eA0 = 0.f, eA1 = 0.f, eA2 = 0.f, eA3 = 0.f;
            float eB0 = 0.f, eB1 = 0.f, eB2 = 0.f, eB3 = 0.f;

            #pragma unroll
            for (int s = 0; s < KSTEPS; s++) {
                unsigned a0 = __float_as_uint(ap0[s * 8]);
                unsigned a1 = __float_as_uint(ap1[s * 8]);
                unsigned a2 = (s < 10) ? __float_as_uint(ap0[s * 8 + 4]) : 0u;
                unsigned a3 = (s < 10) ? __float_as_uint(ap1[s * 8 + 4]) : 0u;
                if (s < 6) {
                    mma_tf32(dA0, dA1, dA2, dA3, a0, a1, a2, a3, Bf[0][s][0], Bf[0][s][1]);
                    mma_tf32(eA0, eA1, eA2, eA3, a0, a1, a2, a3, Bf[1][s][0], Bf[1][s][1]);
                } else {
                    mma_tf32(dB0, dB1, dB2, dB3, a0, a1, a2, a3, Bf[0][s][0], Bf[0][s][1]);
                    mma_tf32(eB0, eB1, eB2, eB3, a0, a1, a2, a3, Bf[1][s][0], Bf[1][s][1]);
                }
            }

            float d0 = dA0 + dB0, d1 = dA1 + dB1, d2 = dA2 + dB2, d3 = dA3 + dB3;
            float e0 = eA0 + eB0, e1 = eA1 + eB1, e2 = eA2 + eB2, e3 = eA3 + eB3;

            float x2_0 = __shfl_sync(0xffffffffu, x2r, mt * 16 + lg);
            float x2_1 = __shfl_sync(0xffffffffu, x2r, mt * 16 + 8 + lg);

            const long long grow0 = stage * SLOT_ROWS + mt * 16 + lg;
            const long long grow1 = grow0 + 8;

            if (grow0 < nrows) {
                float* o = out + grow0 * NPROTO;
                *(float2*)(o + c0) = make_float2(fmaf(-2.f, d0, x2_0 + w2a),
                                                 fmaf(-2.f, d1, x2_0 + w2b));
                if (lc == 0)
                    *(float2*)(o + 8) = make_float2(fmaf(-2.f, e0, x2_0 + w2p8),
                                                    fmaf(-2.f, e1, x2_0 + w2p9));
            }
            if (grow1 < nrows) {
                float* o = out + grow1 * NPROTO;
                *(float2*)(o + c0) = make_float2(fmaf(-2.f, d2, x2_1 + w2a),
                                                 fmaf(-2.f, d3, x2_1 + w2b));
                if (lc == 0)
                    *(float2*)(o + 8) = make_float2(fmaf(-2.f, e2, x2_1 + w2p8),
                                                    fmaf(-2.f, e3, x2_1 + w2p9));
            }
        }

        __syncwarp();                       // warp done reading its slot
        issue_stage(jj + 2 * NWARPS, buf);  // refill this private slot
        jj += NWARPS;
        buf ^= 1;
    }
}

extern "C" void kernel_launch(void* const* d_in, const int* in_sizes, int n_in,
                              void* d_out, int out_size) {
    const float* x = (const float*)d_in[0];
    const float* w = (const float*)d_in[1];
    float* out = (float*)d_out;

    const int nrows = in_sizes[0] / K;   // 524288

    static int nsm = 0;
    if (nsm == 0) {
        cudaFuncSetAttribute(rbf_kernel,
                             cudaFuncAttributeMaxDynamicSharedMemorySize,
                             SMEM_BYTES);
        cudaDeviceGetAttribute(&nsm, cudaDevAttrMultiProcessorCount, 0);
        if (nsm <= 0) nsm = 148;
    }

    // 2 CTAs/SM x 4 warps; each warp = private double-buffered TMA pipeline,
    // zero block syncs in the main loop
    rbf_kernel<<<2 * nsm, THREADS, SMEM_BYTES>>>(x, w, out, nrows);
}

// round 16
// speedup vs baseline: 1.0077x; 1.0077x over previous
#include <cuda_runtime.h>

#define K          84
#define CHUNKS     21
#define NPROTO     10
#define THREADS    96            // 3 warps per CTA
#define NWARPS     3
#define BUFS       3             // triple buffer per warp
#define SLOT_ROWS  32
#define SLOT_FLOATS (SLOT_ROWS * K)          // 2688
#define SLOT_BYTES  (SLOT_FLOATS * 4)        // 10752
#define NSLOTS     (NWARPS * BUFS)           // 9
#define KSTEPS     11                        // ceil(84/8)

// smem per CTA: slots[9][SLOT_FLOATS] + w2[16] + mbar[9] -> ~96.9 KB, 2 CTAs/SM
#define SMEM_BYTES (NSLOTS * SLOT_BYTES + 64 + 96)

__device__ __forceinline__ void ffma2(unsigned long long &d,
                                      unsigned long long a,
                                      unsigned long long b) {
    asm("fma.rn.f32x2 %0, %1, %2, %0;" : "+l"(d) : "l"(a), "l"(b));
}
__device__ __forceinline__ float f2lo(unsigned long long v) {
    return __int_as_float((unsigned)(v & 0xffffffffULL));
}
__device__ __forceinline__ float f2hi(unsigned long long v) {
    return __int_as_float((unsigned)(v >> 32));
}

__device__ __forceinline__ void mma_tf32(float &d0, float &d1, float &d2, float &d3,
                                         unsigned a0, unsigned a1, unsigned a2, unsigned a3,
                                         unsigned b0, unsigned b1) {
    asm("mma.sync.aligned.m16n8k8.row.col.f32.tf32.tf32.f32 "
        "{%0,%1,%2,%3},{%4,%5,%6,%7},{%8,%9},{%0,%1,%2,%3};"
        : "+f"(d0), "+f"(d1), "+f"(d2), "+f"(d3)
        : "r"(a0), "r"(a1), "r"(a2), "r"(a3), "r"(b0), "r"(b1));
}

__device__ __forceinline__ void mbar_init(unsigned mbar, unsigned count) {
    asm volatile("mbarrier.init.shared.b64 [%0], %1;" :: "r"(mbar), "r"(count) : "memory");
}
__device__ __forceinline__ void mbar_expect_tx(unsigned mbar, unsigned bytes) {
    asm volatile("mbarrier.arrive.expect_tx.shared.b64 _, [%0], %1;"
                 :: "r"(mbar), "r"(bytes) : "memory");
}
__device__ __forceinline__ void mbar_wait(unsigned mbar, unsigned parity) {
    unsigned done;
    asm volatile(
        "{\n\t"
        ".reg .pred p;\n\t"
        "mbarrier.try_wait.parity.acquire.cta.shared::cta.b64 p, [%1], %2;\n\t"
        "selp.b32 %0, 1, 0, p;\n\t"
        "}" : "=r"(done) : "r"(mbar), "r"(parity) : "memory");
    if (!done) {
        asm volatile(
            "{\n\t"
            ".reg .pred P1;\n\t"
            "WAIT_LOOP_%=:\n\t"
            "mbarrier.try_wait.parity.acquire.cta.shared::cta.b64 P1, [%0], %1, 0x989680;\n\t"
            "@P1 bra.uni WAIT_DONE_%=;\n\t"
            "bra.uni WAIT_LOOP_%=;\n\t"
            "WAIT_DONE_%=:\n\t"
            "}" :: "r"(mbar), "r"(parity) : "memory");
    }
}
__device__ __forceinline__ void bulk_g2s(unsigned dst_smem, const void* src,
                                         unsigned bytes, unsigned mbar) {
    asm volatile(
        "cp.async.bulk.shared::cta.global.mbarrier::complete_tx::bytes "
        "[%0], [%1], %2, [%3];"
        :: "r"(dst_smem), "l"(src), "r"(bytes), "r"(mbar) : "memory");
}

__global__ void __launch_bounds__(THREADS, 2)
rbf_kernel(const float* __restrict__ x,
           const float* __restrict__ weight,
           float* __restrict__ out,
           int nrows) {
    extern __shared__ __align__(16) float smem[];
    float* s_slots = smem;                                     // [9][SLOT_FLOATS]
    float* s_w2    = smem + NSLOTS * SLOT_FLOATS;              // [16]
    unsigned long long* s_mbar = (unsigned long long*)(s_w2 + 16); // [9]

    const int t    = threadIdx.x;
    const int lane = t & 31;
    const int warp = t / 32;       // 0..2
    const int lg   = lane >> 2;    // 0..7
    const int lc   = lane & 3;     // 0..3

    // ---- B fragments in registers (row.col): proto = nt*8+lg, k = s*8+lc ----
    unsigned Bf[2][KSTEPS][2];
    #pragma unroll
    for (int nt = 0; nt < 2; nt++) {
        int proto = nt * 8 + lg;
        bool pv = proto < NPROTO;
        #pragma unroll
        for (int s = 0; s < KSTEPS; s++) {
            int k0 = s * 8 + lc;
            Bf[nt][s][0] = (pv && k0 < K)     ? __float_as_uint(weight[proto * K + k0])     : 0u;
            Bf[nt][s][1] = (pv && k0 + 4 < K) ? __float_as_uint(weight[proto * K + k0 + 4]) : 0u;
        }
    }

    if (t < NPROTO) {
        float s = 0.f;
        #pragma unroll
        for (int j = 0; j < K; j++) { float w = weight[t * K + j]; s += w * w; }
        s_w2[t] = s;
    }
    if (t >= NPROTO && t < 16) s_w2[t] = 0.f;

    const unsigned mb_base = (unsigned)__cvta_generic_to_shared(&s_mbar[0]);
    const unsigned sl_base = (unsigned)__cvta_generic_to_shared(s_slots);
    if (t < NSLOTS) mbar_init(mb_base + t * 8, 1);

    __syncthreads();   // w2 + mbarriers visible; only block sync

    const int   c0   = 2 * lc;
    const float w2a  = s_w2[c0];
    const float w2b  = s_w2[c0 + 1];
    const float w2p8 = s_w2[8];
    const float w2p9 = s_w2[9];

    const int nstages = (nrows + SLOT_ROWS - 1) / SLOT_ROWS;  // 16384
    const int step = gridDim.x;                               // 2*nsm
    int count = 0;
    for (long long s = blockIdx.x; s < nstages; s += step) count++;

    // warp-private: slot = warp*BUFS + buf
    auto issue_stage = [&](int j, int buf) {
        if (lane == 0 && j < count) {
            int slot = warp * BUFS + buf;
            long long stage = (long long)blockIdx.x + (long long)j * step;
            long long row0 = stage * SLOT_ROWS;
            long long rem_rows = (long long)nrows - row0;
            unsigned bytes = (rem_rows >= SLOT_ROWS)
                           ? SLOT_BYTES
                           : (unsigned)(rem_rows * K * 4);
            mbar_expect_tx(mb_base + slot * 8, bytes);
            bulk_g2s(sl_base + slot * SLOT_BYTES, x + row0 * K, bytes,
                     mb_base + slot * 8);
        }
    };

    // ---- prologue: each warp fills its 3 private slots ----
    issue_stage(warp,              0);
    issue_stage(warp + NWARPS,     1);
    issue_stage(warp + 2 * NWARPS, 2);

    int jj = warp;
    int buf = 0;
    int parity = 0;   // slot s reused every BUFS iterations; flip on wrap

    while (jj < count) {
        const int slot = warp * BUFS + buf;
        mbar_wait(mb_base + slot * 8, (unsigned)parity);

        const long long stage = (long long)blockIdx.x + (long long)jj * step;
        const float* sx = s_slots + slot * SLOT_FLOATS;

        // ---- x2: one row per lane ----
        float x2r;
        {
            const ulonglong2* rp = (const ulonglong2*)(sx + lane * K);
            unsigned long long a0 = 0ULL, a1 = 0ULL;
            #pragma unroll
            for (int c = 0; c < CHUNKS; c++) {
                ulonglong2 v = rp[c];
                ffma2(a0, v.x, v.x);
                ffma2(a1, v.y, v.y);
            }
            x2r = (f2lo(a0) + f2hi(a0)) + (f2lo(a1) + f2hi(a1));
        }

        // ---- two 16-row MMA tiles (rows 0-15, 16-31 of slot) ----
        #pragma unroll
        for (int mt = 0; mt < 2; mt++) {
            const float* ap0 = sx + (mt * 16 + lg) * K + lc;
            const float* ap1 = ap0 + 8 * K;

            float dA0 = 0.f, dA1 = 0.f, dA2 = 0.f, dA3 = 0.f;
            float dB0 = 0.f, dB1 = 0.f, dB2 = 0.f, dB3 = 0.f;
            float eA0 = 0.f, eA1 = 0.f, eA2 = 0.f, eA3 = 0.f;
            float eB0 = 0.f, eB1 = 0.f, eB2 = 0.f, eB3 = 0.f;

            #pragma unroll
            for (int s = 0; s < KSTEPS; s++) {
                unsigned a0 = __float_as_uint(ap0[s * 8]);
                unsigned a1 = __float_as_uint(ap1[s * 8]);
                unsigned a2 = (s < 10) ? __float_as_uint(ap0[s * 8 + 4]) : 0u;
                unsigned a3 = (s < 10) ? __float_as_uint(ap1[s * 8 + 4]) : 0u;
                if (s < 6) {
                    mma_tf32(dA0, dA1, dA2, dA3, a0, a1, a2, a3, Bf[0][s][0], Bf[0][s][1]);
                    mma_tf32(eA0, eA1, eA2, eA3, a0, a1, a2, a3, Bf[1][s][0], Bf[1][s][1]);
                } else {
                    mma_tf32(dB0, dB1, dB2, dB3, a0, a1, a2, a3, Bf[0][s][0], Bf[0][s][1]);
                    mma_tf32(eB0, eB1, eB2, eB3, a0, a1, a2, a3, Bf[1][s][0], Bf[1][s][1]);
                }
            }

            float d0 = dA0 + dB0, d1 = dA1 + dB1, d2 = dA2 + dB2, d3 = dA3 + dB3;
            float e0 = eA0 + eB0, e1 = eA1 + eB1, e2 = eA2 + eB2, e3 = eA3 + eB3;

            float x2_0 = __shfl_sync(0xffffffffu, x2r, mt * 16 + lg);
            float x2_1 = __shfl_sync(0xffffffffu, x2r, mt * 16 + 8 + lg);

            const long long grow0 = stage * SLOT_ROWS + mt * 16 + lg;
            const long long grow1 = grow0 + 8;

            if (grow0 < nrows) {
                float* o = out + grow0 * NPROTO;
                *(float2*)(o + c0) = make_float2(fmaf(-2.f, d0, x2_0 + w2a),
                                                 fmaf(-2.f, d1, x2_0 + w2b));
                if (lc == 0)
                    *(float2*)(o + 8) = make_float2(fmaf(-2.f, e0, x2_0 + w2p8),
                                                    fmaf(-2.f, e1, x2_0 + w2p9));
            }
            if (grow1 < nrows) {
                float* o = out + grow1 * NPROTO;
                *(float2*)(o + c0) = make_float2(fmaf(-2.f, d2, x2_1 + w2a),
                                                 fmaf(-2.f, d3, x2_1 + w2b));
                if (lc == 0)
                    *(float2*)(o + 8) = make_float2(fmaf(-2.f, e2, x2_1 + w2p8),
                                                    fmaf(-2.f, e3, x2_1 + w2p9));
            }
        }

        __syncwarp();                          // warp done reading its slot
        issue_stage(jj + BUFS * NWARPS, buf);  // refill this private slot (stage +9)
        jj += NWARPS;
        if (++buf == BUFS) { buf = 0; parity ^= 1; }
    }
}

extern "C" void kernel_launch(void* const* d_in, const int* in_sizes, int n_in,
                              void* d_out, int out_size) {
    const float* x = (const float*)d_in[0];
    const float* w = (const float*)d_in[1];
    float* out = (float*)d_out;

    const int nrows = in_sizes[0] / K;   // 524288

    static int nsm = 0;
    if (nsm == 0) {
        cudaFuncSetAttribute(rbf_kernel,
                             cudaFuncAttributeMaxDynamicSharedMemorySize,
                             SMEM_BYTES);
        cudaDeviceGetAttribute(&nsm, cudaDevAttrMultiProcessorCount, 0);
        if (nsm <= 0) nsm = 148;
    }

    // 2 CTAs/SM x 3 warps; each warp = private TRIPLE-buffered TMA pipeline
    rbf_kernel<<<2 * nsm, THREADS, SMEM_BYTES>>>(x, w, out, nrows);
}

// round 17
// speedup vs baseline: 1.0643x; 1.0561x over previous
#include <cuda_runtime.h>

#define K          84
#define CHUNKS     21
#define NPROTO     10
#define THREADS    128           // 4 warps per CTA
#define NWARPS     4
#define SLOT_ROWS  32
#define SLOT_FLOATS (SLOT_ROWS * K)          // 2688
#define SLOT_BYTES  (SLOT_FLOATS * 4)        // 10752
#define NSLOTS     8                          // 4 warps x 2 bufs
#define KSTEPS     11
#define OUT_FLOATS (SLOT_ROWS * NPROTO)      // 320 floats = 1280 B

// smem per CTA: slots[8] + w2[16] + mbar[8] + outstage[4][2][OUT_FLOATS]
#define SMEM_BYTES (NSLOTS * SLOT_BYTES + 64 + 64 + NWARPS * 2 * OUT_FLOATS * 4)

__device__ __forceinline__ void ffma2(unsigned long long &d,
                                      unsigned long long a,
                                      unsigned long long b) {
    asm("fma.rn.f32x2 %0, %1, %2, %0;" : "+l"(d) : "l"(a), "l"(b));
}
__device__ __forceinline__ float f2lo(unsigned long long v) {
    return __int_as_float((unsigned)(v & 0xffffffffULL));
}
__device__ __forceinline__ float f2hi(unsigned long long v) {
    return __int_as_float((unsigned)(v >> 32));
}

__device__ __forceinline__ void mma_tf32(float &d0, float &d1, float &d2, float &d3,
                                         unsigned a0, unsigned a1, unsigned a2, unsigned a3,
                                         unsigned b0, unsigned b1) {
    asm("mma.sync.aligned.m16n8k8.row.col.f32.tf32.tf32.f32 "
        "{%0,%1,%2,%3},{%4,%5,%6,%7},{%8,%9},{%0,%1,%2,%3};"
        : "+f"(d0), "+f"(d1), "+f"(d2), "+f"(d3)
        : "r"(a0), "r"(a1), "r"(a2), "r"(a3), "r"(b0), "r"(b1));
}

__device__ __forceinline__ void mbar_init(unsigned mbar, unsigned count) {
    asm volatile("mbarrier.init.shared.b64 [%0], %1;" :: "r"(mbar), "r"(count) : "memory");
}
__device__ __forceinline__ void mbar_expect_tx(unsigned mbar, unsigned bytes) {
    asm volatile("mbarrier.arrive.expect_tx.shared.b64 _, [%0], %1;"
                 :: "r"(mbar), "r"(bytes) : "memory");
}
__device__ __forceinline__ void mbar_wait(unsigned mbar, unsigned parity) {
    unsigned done;
    asm volatile(
        "{\n\t"
        ".reg .pred p;\n\t"
        "mbarrier.try_wait.parity.acquire.cta.shared::cta.b64 p, [%1], %2;\n\t"
        "selp.b32 %0, 1, 0, p;\n\t"
        "}" : "=r"(done) : "r"(mbar), "r"(parity) : "memory");
    if (!done) {
        asm volatile(
            "{\n\t"
            ".reg .pred P1;\n\t"
            "WAIT_LOOP_%=:\n\t"
            "mbarrier.try_wait.parity.acquire.cta.shared::cta.b64 P1, [%0], %1, 0x989680;\n\t"
            "@P1 bra.uni WAIT_DONE_%=;\n\t"
            "bra.uni WAIT_LOOP_%=;\n\t"
            "WAIT_DONE_%=:\n\t"
            "}" :: "r"(mbar), "r"(parity) : "memory");
    }
}
// bulk load with L2 evict-first policy
__device__ __forceinline__ void bulk_g2s(unsigned dst_smem, const void* src,
                                         unsigned bytes, unsigned mbar,
                                         unsigned long long pol) {
    asm volatile(
        "cp.async.bulk.shared::cta.global.mbarrier::complete_tx::bytes.L2::cache_hint "
        "[%0], [%1], %2, [%3], %4;"
        :: "r"(dst_smem), "l"(src), "r"(bytes), "r"(mbar), "l"(pol) : "memory");
}
// bulk store smem -> global (bulk_group)
__device__ __forceinline__ void bulk_s2g(void* gdst, unsigned src_smem, unsigned bytes) {
    asm volatile(
        "cp.async.bulk.global.shared::cta.bulk_group [%0], [%1], %2;"
        :: "l"(gdst), "r"(src_smem), "r"(bytes) : "memory");
}
__device__ __forceinline__ void bulk_commit() {
    asm volatile("cp.async.bulk.commit_group;" ::: "memory");
}
__device__ __forceinline__ void bulk_wait_read1() {
    asm volatile("cp.async.bulk.wait_group.read 1;" ::: "memory");
}
__device__ __forceinline__ void bulk_wait_all() {
    asm volatile("cp.async.bulk.wait_group 0;" ::: "memory");
}
__device__ __forceinline__ void fence_async_smem() {
    asm volatile("fence.proxy.async.shared::cta;" ::: "memory");
}

__global__ void __launch_bounds__(THREADS, 2)
rbf_kernel(const float* __restrict__ x,
           const float* __restrict__ weight,
           float* __restrict__ out,
           int nrows) {
    extern __shared__ __align__(16) float smem[];
    float* s_slots = smem;                                      // [8][SLOT_FLOATS]
    float* s_w2    = smem + NSLOTS * SLOT_FLOATS;               // [16]
    unsigned long long* s_mbar = (unsigned long long*)(s_w2 + 16); // [8]
    float* s_out   = (float*)(s_mbar + NSLOTS);                 // [4][2][OUT_FLOATS]

    const int t    = threadIdx.x;
    const int lane = t & 31;
    const int warp = t >> 5;       // 0..3
    const int lg   = lane >> 2;    // 0..7
    const int lc   = lane & 3;     // 0..3

    unsigned long long pol;
    asm("createpolicy.fractional.L2::evict_first.b64 %0, 1.0;" : "=l"(pol));

    // ---- B fragments in registers ----
    unsigned Bf[2][KSTEPS][2];
    #pragma unroll
    for (int nt = 0; nt < 2; nt++) {
        int proto = nt * 8 + lg;
        bool pv = proto < NPROTO;
        #pragma unroll
        for (int s = 0; s < KSTEPS; s++) {
            int k0 = s * 8 + lc;
            Bf[nt][s][0] = (pv && k0 < K)     ? __float_as_uint(weight[proto * K + k0])     : 0u;
            Bf[nt][s][1] = (pv && k0 + 4 < K) ? __float_as_uint(weight[proto * K + k0 + 4]) : 0u;
        }
    }

    if (t < NPROTO) {
        float s = 0.f;
        #pragma unroll
        for (int j = 0; j < K; j++) { float w = weight[t * K + j]; s += w * w; }
        s_w2[t] = s;
    }
    if (t >= NPROTO && t < 16) s_w2[t] = 0.f;

    const unsigned mb_base = (unsigned)__cvta_generic_to_shared(&s_mbar[0]);
    const unsigned sl_base = (unsigned)__cvta_generic_to_shared(s_slots);
    if (t < NSLOTS) mbar_init(mb_base + t * 8, 1);

    __syncthreads();

    const int   c0   = 2 * lc;
    const float w2a  = s_w2[c0];
    const float w2b  = s_w2[c0 + 1];
    const float w2p8 = s_w2[8];
    const float w2p9 = s_w2[9];

    float* my_out0 = s_out + (warp * 2 + 0) * OUT_FLOATS;
    float* my_out1 = s_out + (warp * 2 + 1) * OUT_FLOATS;
    const unsigned my_out_sm0 = (unsigned)__cvta_generic_to_shared(my_out0);
    const unsigned my_out_sm1 = (unsigned)__cvta_generic_to_shared(my_out1);

    const int nstages = (nrows + SLOT_ROWS - 1) / SLOT_ROWS;  // 16384
    const int step = gridDim.x;                               // 2*nsm
    int count = 0;
    for (long long s = blockIdx.x; s < nstages; s += step) count++;

    auto issue_stage = [&](int j, int buf) {
        if (lane == 0 && j < count) {
            int slot = warp * 2 + buf;
            long long stage = (long long)blockIdx.x + (long long)j * step;
            long long row0 = stage * SLOT_ROWS;
            long long rem_rows = (long long)nrows - row0;
            unsigned bytes = (rem_rows >= SLOT_ROWS)
                           ? SLOT_BYTES
                           : (unsigned)(rem_rows * K * 4);
            mbar_expect_tx(mb_base + slot * 8, bytes);
            bulk_g2s(sl_base + slot * SLOT_BYTES, x + row0 * K, bytes,
                     mb_base + slot * 8, pol);
        }
    };

    // ---- prologue: each warp fills its two private slots ----
    issue_stage(warp,          0);
    issue_stage(warp + NWARPS, 1);

    int jj = warp;
    int buf = 0;
    int par0 = 0, par1 = 0;

    while (jj < count) {
        const int slot = warp * 2 + buf;
        const int par = buf ? par1 : par0;
        mbar_wait(mb_base + slot * 8, (unsigned)par);
        if (buf) par1 ^= 1; else par0 ^= 1;

        const long long stage = (long long)blockIdx.x + (long long)jj * step;
        const float* sx = s_slots + slot * SLOT_FLOATS;
        float* ob = buf ? my_out1 : my_out0;

        // out staging buffer must be free (<=1 pending bulk store)
        if (lane == 0) bulk_wait_read1();
        __syncwarp();

        // ---- x2: one row per lane ----
        float x2r;
        {
            const ulonglong2* rp = (const ulonglong2*)(sx + lane * K);
            unsigned long long a0 = 0ULL, a1 = 0ULL;
            #pragma unroll
            for (int c = 0; c < CHUNKS; c++) {
                ulonglong2 v = rp[c];
                ffma2(a0, v.x, v.x);
                ffma2(a1, v.y, v.y);
            }
            x2r = (f2lo(a0) + f2hi(a0)) + (f2lo(a1) + f2hi(a1));
        }

        // ---- two 16-row MMA tiles, results -> smem staging ----
        #pragma unroll
        for (int mt = 0; mt < 2; mt++) {
            const float* ap0 = sx + (mt * 16 + lg) * K + lc;
            const float* ap1 = ap0 + 8 * K;

            float dA0 = 0.f, dA1 = 0.f, dA2 = 0.f, dA3 = 0.f;
            float dB0 = 0.f, dB1 = 0.f, dB2 = 0.f, dB3 = 0.f;
            float eA0 = 0.f, eA1 = 0.f, eA2 = 0.f, eA3 = 0.f;
            float eB0 = 0.f, eB1 = 0.f, eB2 = 0.f, eB3 = 0.f;

            #pragma unroll
            for (int s = 0; s < KSTEPS; s++) {
                unsigned a0 = __float_as_uint(ap0[s * 8]);
                unsigned a1 = __float_as_uint(ap1[s * 8]);
                unsigned a2 = (s < 10) ? __float_as_uint(ap0[s * 8 + 4]) : 0u;
                unsigned a3 = (s < 10) ? __float_as_uint(ap1[s * 8 + 4]) : 0u;
                if (s < 6) {
                    mma_tf32(dA0, dA1, dA2, dA3, a0, a1, a2, a3, Bf[0][s][0], Bf[0][s][1]);
                    mma_tf32(eA0, eA1, eA2, eA3, a0, a1, a2, a3, Bf[1][s][0], Bf[1][s][1]);
                } else {
                    mma_tf32(dB0, dB1, dB2, dB3, a0, a1, a2, a3, Bf[0][s][0], Bf[0][s][1]);
                    mma_tf32(eB0, eB1, eB2, eB3, a0, a1, a2, a3, Bf[1][s][0], Bf[1][s][1]);
                }
            }

            float d0 = dA0 + dB0, d1 = dA1 + dB1, d2 = dA2 + dB2, d3 = dA3 + dB3;
            float e0 = eA0 + eB0, e1 = eA1 + eB1, e2 = eA2 + eB2, e3 = eA3 + eB3;

            float x2_0 = __shfl_sync(0xffffffffu, x2r, mt * 16 + lg);
            float x2_1 = __shfl_sync(0xffffffffu, x2r, mt * 16 + 8 + lg);

            const int r0 = mt * 16 + lg;
            const int r1 = r0 + 8;

            float* o0 = ob + r0 * NPROTO;
            float* o1 = ob + r1 * NPROTO;
            *(float2*)(o0 + c0) = make_float2(fmaf(-2.f, d0, x2_0 + w2a),
                                              fmaf(-2.f, d1, x2_0 + w2b));
            *(float2*)(o1 + c0) = make_float2(fmaf(-2.f, d2, x2_1 + w2a),
                                              fmaf(-2.f, d3, x2_1 + w2b));
            if (lc == 0) {
                *(float2*)(o0 + 8) = make_float2(fmaf(-2.f, e0, x2_0 + w2p8),
                                                 fmaf(-2.f, e1, x2_0 + w2p9));
                *(float2*)(o1 + 8) = make_float2(fmaf(-2.f, e2, x2_1 + w2p8),
                                                 fmaf(-2.f, e3, x2_1 + w2p9));
            }
        }

        __syncwarp();   // staging complete; slot fully read

        if (lane == 0) {
            long long row0 = stage * SLOT_ROWS;
            long long rem_rows = (long long)nrows - row0;
            unsigned obytes = (rem_rows >= SLOT_ROWS)
                            ? (unsigned)(OUT_FLOATS * 4)
                            : (unsigned)(rem_rows * NPROTO * 4);
            fence_async_smem();
            bulk_s2g(out + row0 * NPROTO, buf ? my_out_sm1 : my_out_sm0, obytes);
            bulk_commit();
        }

        issue_stage(jj + 2 * NWARPS, buf);  // refill this private slot
        jj += NWARPS;
        buf ^= 1;
    }

    if (lane == 0) bulk_wait_all();   // drain pending bulk stores
}

extern "C" void kernel_launch(void* const* d_in, const int* in_sizes, int n_in,
                              void* d_out, int out_size) {
    const float* x = (const float*)d_in[0];
    const float* w = (const float*)d_in[1];
    float* out = (float*)d_out;

    const int nrows = in_sizes[0] / K;   // 524288

    static int nsm = 0;
    if (nsm == 0) {
        cudaFuncSetAttribute(rbf_kernel,
                             cudaFuncAttributeMaxDynamicSharedMemorySize,
                             SMEM_BYTES);
        cudaDeviceGetAttribute(&nsm, cudaDevAttrMultiProcessorCount, 0);
        if (nsm <= 0) nsm = 148;
    }

    // R15 base + TMA bulk output stores + L2 evict-first streaming loads
    rbf_kernel<<<2 * nsm, THREADS, SMEM_BYTES>>>(x, w, out, nrows);
}